// round 3
// baseline (speedup 1.0000x reference)
#include <cuda_runtime.h>

#define BB 8
#define TT 512
#define DD 64
#define TILE 64
#define NT (TT / TILE)               // 8 tiles per dim
#define NPAIR (NT * (NT + 1) / 2)    // 36 upper-tri tile pairs
#define PAD 65                        // row pad (floats): conflict-free scalar LDS

// sqrt(log2(e)): pre-scaling x by this lets exp(-(dx)^2) = ex2(-(s*dx)^2)
#define SQRT_LOG2E 1.2011224087864498f

__device__ float g_v[BB * TT * DD];   // scratch: v = x @ W^T + b (512 KB)

__device__ __forceinline__ float ex2f(float x) {
    float r;
    asm("ex2.approx.ftz.f32 %0, %1;" : "=f"(r) : "f"(x));
    return r;
}

// ---------------------------------------------------------------------------
// Kernel 1: v[b,t,e] = sum_d x[b,t,d] * W[e,d] + bias[e]
// 64 blocks x 256 threads; each block covers 64 (b,t) rows. W staged
// transposed [d][e] (stride 68, 16B-aligned) for LDS.128; x rows broadcast.
// Per d-iter per thread: 1 LDS.128 + 4 broadcast LDS + 16 FMA.
// ---------------------------------------------------------------------------
#define WSTR 68
__global__ __launch_bounds__(256)
void v_kernel(const float* __restrict__ x, const float* __restrict__ W,
              const float* __restrict__ bias) {
    __shared__ float sWT[DD * WSTR];     // sWT[d*68 + e] = W[e*64 + d]
    __shared__ float sX[64 * DD];        // 64 rows of x, natural layout

    int tid = threadIdx.x;
    int row0 = blockIdx.x * 64;

    for (int k = tid; k < DD * DD; k += 256) {
        int e = k >> 6, d = k & 63;
        sWT[d * WSTR + e] = W[k];        // coalesced read
    }
    for (int k = tid; k < 64 * DD; k += 256)
        sX[k] = x[row0 * DD + k];
    __syncthreads();

    int eg = tid & 15;                   // e-group: e = 4*eg .. 4*eg+3
    int rs = tid >> 4;                   // row slot 0..15; rows rs+16k
    float4 b4 = *(const float4*)&bias[4 * eg];

    float acc[4][4];
#pragma unroll
    for (int k = 0; k < 4; k++) {
        acc[k][0] = b4.x; acc[k][1] = b4.y; acc[k][2] = b4.z; acc[k][3] = b4.w;
    }

#pragma unroll 4
    for (int d = 0; d < DD; d++) {
        float4 w4 = *(const float4*)&sWT[d * WSTR + 4 * eg];
#pragma unroll
        for (int k = 0; k < 4; k++) {
            float xv = sX[(rs + 16 * k) * DD + d];   // broadcast
            acc[k][0] = fmaf(xv, w4.x, acc[k][0]);
            acc[k][1] = fmaf(xv, w4.y, acc[k][1]);
            acc[k][2] = fmaf(xv, w4.z, acc[k][2]);
            acc[k][3] = fmaf(xv, w4.w, acc[k][3]);
        }
    }

#pragma unroll
    for (int k = 0; k < 4; k++) {
        float4 o = make_float4(acc[k][0], acc[k][1], acc[k][2], acc[k][3]);
        *(float4*)&g_v[(row0 + rs + 16 * k) * DD + 4 * eg] = o;
    }
}

// ---------------------------------------------------------------------------
// Kernel 2: pairwise RBF softmax-weighted output with (i,j) symmetry.
// Block = (b, upper-tri pair of 64x64 tiles), 512 threads. Thread (tx,ty)
// owns i rows {ty, ty+32} and j cols {tx, tx+16, tx+32, tx+48}: bank index
// (tx + 16c + d) mod 32 is conflict-free across the 16 tx-lanes, and main
// writes are coalesced across tx for each c. x pre-scaled by sqrt(log2 e)
// so exp costs FMUL(neg) + MUFU.EX2.
// ---------------------------------------------------------------------------
__global__ __launch_bounds__(512)
void rbf_kernel(const float* __restrict__ x, float* __restrict__ out) {
    extern __shared__ float smem[];
    float* xi = smem;                          // TILE*PAD each
    float* xj = xi + TILE * PAD;
    float* vi = xj + TILE * PAD;
    float* vj = vi + TILE * PAD;

    int b = blockIdx.y;
    int p = blockIdx.x;
    int ti = 0, rem = p;
    while (rem >= NT - ti) { rem -= NT - ti; ti++; }
    int tj = ti + rem;
    int i0 = ti * TILE, j0 = tj * TILE;

    int tid = threadIdx.x;
    const float* xb = x + b * TT * DD;
    const float* vb = g_v + b * TT * DD;

#pragma unroll
    for (int k = 0; k < 8; k++) {
        int idx = tid + k * 512;               // [0, 4096)
        int r = idx >> 6, d = idx & 63;
        int sa = r * PAD + d;
        xi[sa] = SQRT_LOG2E * xb[i0 * DD + idx];
        xj[sa] = SQRT_LOG2E * xb[j0 * DD + idx];
        vi[sa] = vb[i0 * DD + idx];
        vj[sa] = vb[j0 * DD + idx];
    }
    __syncthreads();

    int tx = tid & 15, ty = tid >> 4;          // ty 0..31

    float den[2][4], ni[2][4], nj[2][4];
#pragma unroll
    for (int r = 0; r < 2; r++)
#pragma unroll
        for (int c = 0; c < 4; c++) { den[r][c] = 0.f; ni[r][c] = 0.f; nj[r][c] = 0.f; }

#pragma unroll 2
    for (int d = 0; d < DD; d++) {
        float fi[2], fv[2], fj[4], jv[4];
#pragma unroll
        for (int r = 0; r < 2; r++) {
            int row = ty + 32 * r;
            fi[r] = xi[row * PAD + d];          // broadcast (2 addrs/warp)
            fv[r] = vi[row * PAD + d];
        }
#pragma unroll
        for (int c = 0; c < 4; c++) {
            int col = tx + 16 * c;
            fj[c] = xj[col * PAD + d];          // conflict-free across tx
            jv[c] = vj[col * PAD + d];
        }
#pragma unroll
        for (int r = 0; r < 2; r++) {
#pragma unroll
            for (int c = 0; c < 4; c++) {
                float dd = fi[r] - fj[c];
                float e  = ex2f(-dd * dd);      // FMUL(src-neg) + MUFU.EX2
                den[r][c] += e;
                ni[r][c] = fmaf(e, fv[r], ni[r][c]);
                nj[r][c] = fmaf(e, jv[c], nj[r][c]);
            }
        }
    }

    float* ob = out + (size_t)b * TT * TT;

#pragma unroll
    for (int r = 0; r < 2; r++) {
        int gi = i0 + ty + 32 * r;
#pragma unroll
        for (int c = 0; c < 4; c++) {
            int gj = j0 + tx + 16 * c;
            float rc;
            asm("rcp.approx.ftz.f32 %0, %1;" : "=f"(rc) : "f"(den[r][c]));
            // main: coalesced across tx
            ob[(size_t)gi * TT + gj] = ni[r][c] * rc;
            if (ti != tj)
                ob[(size_t)gj * TT + gi] = nj[r][c] * rc;   // mirror
        }
    }
}

extern "C" void kernel_launch(void* const* d_in, const int* in_sizes, int n_in,
                              void* d_out, int out_size) {
    const float* x = (const float*)d_in[0];    // (8,512,64)
    const float* W = (const float*)d_in[1];    // (64,64)
    const float* bias = (const float*)d_in[2]; // (64,)
    float* out = (float*)d_out;                // (8,512,512)

    static bool attr_set = false;
    size_t smem_bytes = 4 * TILE * PAD * sizeof(float);   // 66560
    if (!attr_set) {
        cudaFuncSetAttribute(rbf_kernel,
                             cudaFuncAttributeMaxDynamicSharedMemorySize,
                             (int)smem_bytes);
        attr_set = true;
    }

    v_kernel<<<(BB * TT) / 64, 256>>>(x, W, bias);
    rbf_kernel<<<dim3(NPAIR, BB), 512, smem_bytes>>>(x, out);
}

// round 4
// speedup vs baseline: 1.2391x; 1.2391x over previous
#include <cuda_runtime.h>

#define BB 8
#define TT 512
#define DD 64
#define TILE 64
#define NT (TT / TILE)               // 8 tiles per dim
#define NPAIR (NT * (NT + 1) / 2)    // 36 upper-tri tile pairs
#define TSTR 66                       // transposed [d][row] stride (floats)

// sqrt(log2(e)): pre-scale x so exp(-(dx)^2) = ex2(-(s*dx)^2)
#define SQRT_LOG2E 1.2011224087864498f

typedef unsigned long long u64;

__device__ float g_v[BB * TT * DD];   // scratch: v = x @ W^T + b (512 KB)

// ---- f32x2 packed helpers (sm_103a) --------------------------------------
__device__ __forceinline__ u64 pack2(float lo, float hi) {
    u64 r; asm("mov.b64 %0, {%1, %2};" : "=l"(r) : "f"(lo), "f"(hi)); return r;
}
__device__ __forceinline__ void unpack2(u64 v, float& lo, float& hi) {
    asm("mov.b64 {%0, %1}, %2;" : "=f"(lo), "=f"(hi) : "l"(v));
}
__device__ __forceinline__ u64 add2(u64 a, u64 b) {
    u64 r; asm("add.rn.f32x2 %0, %1, %2;" : "=l"(r) : "l"(a), "l"(b)); return r;
}
__device__ __forceinline__ u64 mul2(u64 a, u64 b) {
    u64 r; asm("mul.rn.f32x2 %0, %1, %2;" : "=l"(r) : "l"(a), "l"(b)); return r;
}
__device__ __forceinline__ u64 fma2(u64 a, u64 b, u64 c) {
    u64 r; asm("fma.rn.f32x2 %0, %1, %2, %3;" : "=l"(r) : "l"(a), "l"(b), "l"(c)); return r;
}
// ex2(-m): sign flip via LOP3 (ALU pipe) + MUFU.EX2
__device__ __forceinline__ float ex2negf(float m) {
    float nm = __uint_as_float(__float_as_uint(m) ^ 0x80000000u);
    float r; asm("ex2.approx.ftz.f32 %0, %1;" : "=f"(r) : "f"(nm)); return r;
}

// ---------------------------------------------------------------------------
// Kernel 1: v[b,t,e] = sum_d x[b,t,d] * W[e,d] + bias[e]
// 256 blocks x 256 threads, 16 rows/block. Thread = (e-group of 4, row).
// Per d: 1 LDS.128 (W) + 1 broadcast LDS (x) + 4 FFMA.
// ---------------------------------------------------------------------------
#define WSTR 68
__global__ __launch_bounds__(256)
void v_kernel(const float* __restrict__ x, const float* __restrict__ W,
              const float* __restrict__ bias) {
    __shared__ float sWT[DD * WSTR];     // sWT[d*68 + e] = W[e*64 + d]
    __shared__ float sX[16 * DD];

    int tid = threadIdx.x;
    int row0 = blockIdx.x * 16;

    for (int k = tid; k < DD * DD; k += 256) {
        int e = k >> 6, d = k & 63;
        sWT[d * WSTR + e] = W[k];        // coalesced global read
    }
    for (int k = tid; k < 16 * DD; k += 256)
        sX[k] = x[row0 * DD + k];
    __syncthreads();

    int eg = tid & 15;                   // e = 4*eg .. 4*eg+3
    int rs = tid >> 4;                   // row 0..15
    float4 acc = *(const float4*)&bias[4 * eg];

#pragma unroll 8
    for (int d = 0; d < DD; d++) {
        float4 w4 = *(const float4*)&sWT[d * WSTR + 4 * eg];
        float xv = sX[rs * DD + d];      // broadcast
        acc.x = fmaf(xv, w4.x, acc.x);
        acc.y = fmaf(xv, w4.y, acc.y);
        acc.z = fmaf(xv, w4.z, acc.z);
        acc.w = fmaf(xv, w4.w, acc.w);
    }
    *(float4*)&g_v[(row0 + rs) * DD + 4 * eg] = acc;
}

// ---------------------------------------------------------------------------
// Kernel 2: pairwise RBF with (i,j) symmetry, f32x2 packed inner loop.
// Block = (b, upper-tri 64x64 tile pair), 256 threads, 4x4 elems/thread.
// Thread (tx,ty): i rows {2ty,2ty+1,2ty+32,2ty+33}, j cols packed in pairs
// {2tx,2tx+1} and {2tx+32,2tx+33}. Arrays transposed [d][row] (stride 66):
// all inner-loop LDS.64 are broadcast or fully spread -> conflict-free.
// XJ is staged NEGATED so the pair-difference is a single add.rn.f32x2.
// ---------------------------------------------------------------------------
__global__ __launch_bounds__(256, 2)
void rbf_kernel(const float* __restrict__ x, float* __restrict__ out) {
    extern __shared__ float smem[];
    float* XI  = smem;                   // +s*xi   [d*66 + row]
    float* NXJ = XI  + DD * TSTR;        // -s*xj
    float* VI  = NXJ + DD * TSTR;
    float* VJ  = VI  + DD * TSTR;

    int b = blockIdx.y;
    int p = blockIdx.x;
    int ti = 0, rem = p;
    while (rem >= NT - ti) { rem -= NT - ti; ti++; }
    int tj = ti + rem;
    int i0 = ti * TILE, j0 = tj * TILE;

    int tid = threadIdx.x;
    const float* xb = x + b * TT * DD;
    const float* vb = g_v + b * TT * DD;

    // Stage transposed. idx: r = idx>>6, d = idx&63 -> coalesced global,
    // STS bank (2d+r)%32 -> 2-way (negligible, staging only).
#pragma unroll
    for (int k = 0; k < 16; k++) {
        int idx = tid + k * 256;
        int r = idx >> 6, d = idx & 63;
        int sa = d * TSTR + r;
        float xiv = xb[i0 * DD + idx];
        float xjv = xb[j0 * DD + idx];
        XI[sa]  =  SQRT_LOG2E * xiv;
        NXJ[sa] = -SQRT_LOG2E * xjv;
        VI[sa]  = vb[i0 * DD + idx];
        VJ[sa]  = vb[j0 * DD + idx];
    }
    __syncthreads();

    int tx = tid & 15, ty = tid >> 4;

    u64 den[4][2], ni[4][2], nj[4][2];
#pragma unroll
    for (int r = 0; r < 4; r++)
#pragma unroll
        for (int c = 0; c < 2; c++) { den[r][c] = 0ULL; ni[r][c] = 0ULL; nj[r][c] = 0ULL; }

#pragma unroll 2
    for (int d = 0; d < DD; d++) {
        const float* XId  = XI  + d * TSTR;
        const float* VId  = VI  + d * TSTR;
        const float* NXJd = NXJ + d * TSTR;
        const float* VJd  = VJ  + d * TSTR;

        float2 fiA = *(const float2*)&XId[2 * ty];        // broadcast
        float2 fiB = *(const float2*)&XId[2 * ty + 32];
        float2 fvA = *(const float2*)&VId[2 * ty];
        float2 fvB = *(const float2*)&VId[2 * ty + 32];
        u64 njc0 = *(const u64*)&NXJd[2 * tx];            // spread, conflict-free
        u64 njc1 = *(const u64*)&NXJd[2 * tx + 32];
        u64 jvc0 = *(const u64*)&VJd[2 * tx];
        u64 jvc1 = *(const u64*)&VJd[2 * tx + 32];

        float fi[4] = {fiA.x, fiA.y, fiB.x, fiB.y};
        float fv[4] = {fvA.x, fvA.y, fvB.x, fvB.y};
        u64 njc[2] = {njc0, njc1};
        u64 jvc[2] = {jvc0, jvc1};

#pragma unroll
        for (int r = 0; r < 4; r++) {
            u64 fid = pack2(fi[r], fi[r]);
            u64 fvd = pack2(fv[r], fv[r]);
#pragma unroll
            for (int c = 0; c < 2; c++) {
                u64 a2 = add2(fid, njc[c]);      // s*(xi - xj), 2 elems
                u64 m2 = mul2(a2, a2);           // +dd^2
                float m0, m1; unpack2(m2, m0, m1);
                float e0 = ex2negf(m0);          // LOP3 + MUFU.EX2
                float e1 = ex2negf(m1);
                u64 e2 = pack2(e0, e1);
                den[r][c] = add2(den[r][c], e2);
                ni[r][c]  = fma2(e2, fvd, ni[r][c]);
                nj[r][c]  = fma2(e2, jvc[c], nj[r][c]);
            }
        }
    }

    float* ob = out + (size_t)b * TT * TT;
    int rowOf[4] = {2 * ty, 2 * ty + 1, 2 * ty + 32, 2 * ty + 33};

    // per-element reciprocals + outputs
    float oi[4][2][2], oj[4][2][2];
#pragma unroll
    for (int r = 0; r < 4; r++)
#pragma unroll
        for (int c = 0; c < 2; c++) {
            float d0, d1, n0, n1, q0, q1;
            unpack2(den[r][c], d0, d1);
            unpack2(ni[r][c],  n0, n1);
            unpack2(nj[r][c],  q0, q1);
            float rc0, rc1;
            asm("rcp.approx.ftz.f32 %0, %1;" : "=f"(rc0) : "f"(d0));
            asm("rcp.approx.ftz.f32 %0, %1;" : "=f"(rc1) : "f"(d1));
            oi[r][c][0] = n0 * rc0; oi[r][c][1] = n1 * rc1;
            oj[r][c][0] = q0 * rc0; oj[r][c][1] = q1 * rc1;
        }

    // main writes: out[b, gi, j0+2tx+32c .. +1] — float2, coalesced across tx
#pragma unroll
    for (int r = 0; r < 4; r++) {
        int gi = i0 + rowOf[r];
#pragma unroll
        for (int c = 0; c < 2; c++) {
            float2 w = make_float2(oi[r][c][0], oi[r][c][1]);
            *(float2*)&ob[(size_t)gi * TT + j0 + 2 * tx + 32 * c] = w;
        }
    }

    if (ti != tj) {
        // mirror: out[b, gj, gi..gi+1] — float2 over the r-pairs
#pragma unroll
        for (int c = 0; c < 2; c++) {
#pragma unroll
            for (int e = 0; e < 2; e++) {
                int gj = j0 + 2 * tx + 32 * c + e;
                float2 w0 = make_float2(oj[0][c][e], oj[1][c][e]);
                float2 w1 = make_float2(oj[2][c][e], oj[3][c][e]);
                *(float2*)&ob[(size_t)gj * TT + i0 + 2 * ty]      = w0;
                *(float2*)&ob[(size_t)gj * TT + i0 + 2 * ty + 32] = w1;
            }
        }
    }
}

extern "C" void kernel_launch(void* const* d_in, const int* in_sizes, int n_in,
                              void* d_out, int out_size) {
    const float* x = (const float*)d_in[0];    // (8,512,64)
    const float* W = (const float*)d_in[1];    // (64,64)
    const float* bias = (const float*)d_in[2]; // (64,)
    float* out = (float*)d_out;                // (8,512,512)

    static bool attr_set = false;
    size_t smem_bytes = 4 * DD * TSTR * sizeof(float);   // 67584
    if (!attr_set) {
        cudaFuncSetAttribute(rbf_kernel,
                             cudaFuncAttributeMaxDynamicSharedMemorySize,
                             (int)smem_bytes);
        attr_set = true;
    }

    v_kernel<<<(BB * TT) / 16, 256>>>(x, W, bias);
    rbf_kernel<<<dim3(NPAIR, BB), 256, smem_bytes>>>(x, out);
}